// round 6
// baseline (speedup 1.0000x reference)
#include <cuda_runtime.h>
#include <math.h>

#define GX 200
#define GY 200
#define GZ 16
#define NVOX (GX*GY*GZ)
#define F_N 8
#define NQ (NVOX * 2)        // number of feature float4s
#define NORM_ILP 4
#define NORM_THREADS (NQ / NORM_ILP)   // 320000, NQ divisible by 4

__device__ __forceinline__ void red_add_v4(float* p, float a, float b, float c, float d) {
    asm volatile("red.global.add.v4.f32 [%0], {%1,%2,%3,%4};"
                 :: "l"(p), "f"(a), "f"(b), "f"(c), "f"(d) : "memory");
}

__global__ void gv_splat_kernel(const float* __restrict__ means,
                                const float* __restrict__ opac,
                                const float* __restrict__ cov,
                                const float* __restrict__ feat,
                                float* __restrict__ out,
                                int G) {
    int gwarp = (blockIdx.x * blockDim.x + threadIdx.x) >> 5;
    if (gwarp >= G) return;
    int lane = threadIdx.x & 31;

    const float lox = -40.f, loy = -40.f, loz = -1.f;
    const float hix =  40.f, hiy =  40.f, hiz =  5.4f;
    const float VOX = 0.4f;

    float mx = means[gwarp*3 + 0];
    float my = means[gwarp*3 + 1];
    float mz = means[gwarp*3 + 2];
    const float* C = cov + (size_t)gwarp * 9;
    float c00 = C[0], c01 = C[1], c02 = C[2];
    float c11 = C[4], c12 = C[5], c22 = C[8];

    float sx = sqrtf(c00), sy = sqrtf(c11), sz = sqrtf(c22);
    float blx = mx - 3.f*sx, bly = my - 3.f*sy, blz = mz - 3.f*sz;
    float bhx = mx + 3.f*sx, bhy = my + 3.f*sy, bhz = mz + 3.f*sz;

    bool valid = (bhx > lox) && (bhy > loy) && (bhz > loz) &&
                 (blx < hix) && (bly < hiy) && (blz < hiz);
    if (!valid) return;

    float blxc = fminf(fmaxf(blx, lox), hix);
    float blyc = fminf(fmaxf(bly, loy), hiy);
    float blzc = fminf(fmaxf(blz, loz), hiz);
    float bhxc = fminf(fmaxf(bhx, lox), hix);
    float bhyc = fminf(fmaxf(bhy, loy), hiy);
    float bhzc = fminf(fmaxf(bhz, loz), hiz);

    int ilox = min((int)((blxc - lox) / VOX), GX - 1);
    int iloy = min((int)((blyc - loy) / VOX), GY - 1);
    int iloz = min((int)((blzc - loz) / VOX), GZ - 1);
    int ihix = min((int)((bhxc - lox) / VOX), GX - 1);
    int ihiy = min((int)((bhyc - loy) / VOX), GY - 1);
    int ihiz = min((int)((bhzc - loz) / VOX), GZ - 1);

    int nx = ihix - ilox + 1;
    int ny = ihiy - iloy + 1;

    // symmetric 3x3 inverse (adjugate / det)
    float i00 = c11*c22 - c12*c12;
    float i01 = c02*c12 - c01*c22;
    float i02 = c01*c12 - c02*c11;
    float i11 = c00*c22 - c02*c02;
    float i12 = c01*c02 - c00*c12;
    float i22 = c00*c11 - c01*c01;
    float det = c00*i00 + c01*i01 + c02*i02;
    float rdet = 1.f / det;
    float a00 = i00*rdet, a01 = i01*rdet, a02 = i02*rdet;
    float a11 = i11*rdet, a12 = i12*rdet, a22 = i22*rdet;

    float op = opac[gwarp];
    float f[F_N];
#pragma unroll
    for (int k = 0; k < F_N; k++) f[k] = feat[(size_t)gwarp*F_N + k];

    float* dgrid = out;
    float* fgrid = out + NVOX;

    int z0 = iloz & ~3;   // aligned start of z quads (GZ=16 -> quads never cross columns)

    int npairs = nx * ny;
    for (int p = lane; p < npairs; p += 32) {
        int ox = p / ny;
        int oy = p - ox * ny;
        int ix = ilox + ox;
        int iy = iloy + oy;
        float dx = ((float)ix + 0.5f) * VOX + lox - mx;
        float dy = ((float)iy + 0.5f) * VOX + loy - my;
        float cxy  = a00*dx*dx + a11*dy*dy + 2.f*a01*dx*dy;
        float clin = 2.f*(a02*dx + a12*dy);
        int colBase = (ix * GY + iy) * GZ;

        for (int zb = z0; zb <= ihiz; zb += 4) {
            float dvq[4];
#pragma unroll
            for (int j = 0; j < 4; j++) {
                int iz = zb + j;
                float dv = 0.f;
                if (iz >= iloz && iz <= ihiz) {
                    float dz = ((float)iz + 0.5f) * VOX + loz - mz;
                    float maha = cxy + dz * (clin + a22 * dz);
                    dv = op * __expf(-0.5f * maha);
                    float* fp = fgrid + (size_t)(colBase + iz) * F_N;
                    red_add_v4(fp,     dv*f[0], dv*f[1], dv*f[2], dv*f[3]);
                    red_add_v4(fp + 4, dv*f[4], dv*f[5], dv*f[6], dv*f[7]);
                }
                dvq[j] = dv;
            }
            // one vector atomic covers 4 consecutive density voxels (16B aligned)
            red_add_v4(dgrid + colBase + zb, dvq[0], dvq[1], dvq[2], dvq[3]);
        }
    }
}

// 4-way ILP: each thread handles 4 strided float4 chunks; all loads issued
// before any dependent math/stores -> 4x memory in flight per thread.
__global__ void gv_norm_kernel(float* __restrict__ out) {
    int t = blockIdx.x * blockDim.x + threadIdx.x;
    if (t >= NORM_THREADS) return;

    const float* dens = out;
    float4* fq = (float4*)(out + NVOX);

    int i0 = t;
    int i1 = t + NORM_THREADS;
    int i2 = t + 2 * NORM_THREADS;
    int i3 = t + 3 * NORM_THREADS;

    float d0 = dens[i0 >> 1];
    float d1 = dens[i1 >> 1];
    float d2 = dens[i2 >> 1];
    float d3 = dens[i3 >> 1];
    float4 a0 = fq[i0];
    float4 a1 = fq[i1];
    float4 a2 = fq[i2];
    float4 a3 = fq[i3];

    float s0 = 1.f / fmaxf(d0, 1e-6f);
    float s1 = 1.f / fmaxf(d1, 1e-6f);
    float s2 = 1.f / fmaxf(d2, 1e-6f);
    float s3 = 1.f / fmaxf(d3, 1e-6f);

    a0.x *= s0; a0.y *= s0; a0.z *= s0; a0.w *= s0;
    a1.x *= s1; a1.y *= s1; a1.z *= s1; a1.w *= s1;
    a2.x *= s2; a2.y *= s2; a2.z *= s2; a2.w *= s2;
    a3.x *= s3; a3.y *= s3; a3.z *= s3; a3.w *= s3;

    fq[i0] = a0;
    fq[i1] = a1;
    fq[i2] = a2;
    fq[i3] = a3;
}

extern "C" void kernel_launch(void* const* d_in, const int* in_sizes, int n_in,
                              void* d_out, int out_size) {
    const float* means = (const float*)d_in[0];   // (G,3)
    const float* opac  = (const float*)d_in[1];   // (G,1)
    const float* cov   = (const float*)d_in[2];   // (G,3,3)
    const float* feat  = (const float*)d_in[3];   // (G,8)
    float* out = (float*)d_out;                   // [640000 density | 5120000 feats]

    int G = in_sizes[0] / 3;

    cudaMemsetAsync(out, 0, (size_t)out_size * sizeof(float));

    int threads = G * 32;  // one warp per gaussian
    gv_splat_kernel<<<(threads + 255) / 256, 256>>>(means, opac, cov, feat, out, G);

    gv_norm_kernel<<<(NORM_THREADS + 255) / 256, 256>>>(out);
}